// round 7
// baseline (speedup 1.0000x reference)
#include <cuda_runtime.h>
#include <cuda_bf16.h>
#include <math.h>
#include <stdint.h>

#define B_    2
#define C_    105
#define L_IN  5500
#define NCH   210
#define D_    512
#define L0_   1831
#define T_    56
#define KCODES 1014
#define SECT  (B_*D_*T_)
#define WSL   262144            // one 512x512 weight k-slice (elements, 2^18)

// plane-row capacities (per buffer geometry, must match producer & consumer)
#define TH0   968               // conv0 out  (A)  L=1831, 6x160 tiles
#define TH1   484               // conv1 out  (B)  L=915,  3x160
#define TH2   260               // conv2 out  (A)  L=457,  2x128
#define TH3   132               // conv3 out  (B)  L=228,  1x128
#define TH4   66                // conv4 out  (A)  L=113,  1x64

// ---------------- device scratch (allocation-free) ----------------
// act layout: [n][ci16 chunk(32)][parity(2)][row<Th][32B], swizzled 16B granules
__device__ __align__(128) __nv_bfloat16  g_hiA[(size_t)NCH * 64 * TH0 * 16];
__device__ __align__(128) __nv_bfloat16  g_loA[(size_t)NCH * 64 * TH0 * 16];
__device__ __align__(128) __nv_bfloat16  g_hiB[(size_t)NCH * 64 * TH1 * 16];
__device__ __align__(128) __nv_bfloat16  g_loB[(size_t)NCH * 64 * TH1 * 16];
__device__ __align__(128) float          g_c5 [(size_t)NCH * D_ * T_];
// weight tiles: [k][ci16 chunk(32)][co 512][32B] swizzled
__device__ __align__(128) __nv_bfloat16  g_whi[14 * WSL];
__device__ __align__(128) __nv_bfloat16  g_wlo[14 * WSL];

// ---------------- helpers ----------------
__device__ __forceinline__ float gelu_exact(float v) {
    return 0.5f * v * (1.0f + erff(v * 0.70710678118654752f));
}
__device__ __forceinline__ uint32_t s2u(const void* p) {
    uint32_t a;
    asm("{ .reg .u64 t; cvta.to.shared.u64 t, %1; cvt.u32.u64 %0, t; }" : "=r"(a) : "l"(p));
    return a;
}
__device__ __forceinline__ void mb_init(uint32_t a, uint32_t c) {
    asm volatile("mbarrier.init.shared.b64 [%0], %1;" :: "r"(a), "r"(c) : "memory");
}
__device__ __forceinline__ void mb_expect(uint32_t a, uint32_t bytes) {
    asm volatile("mbarrier.arrive.expect_tx.shared.b64 _, [%0], %1;" :: "r"(a), "r"(bytes) : "memory");
}
__device__ __forceinline__ void mb_wait(uint32_t a, uint32_t par) {
    asm volatile("{\n\t.reg .pred P;\n\tWL%=:\n\t"
                 "mbarrier.try_wait.parity.acquire.cta.shared::cta.b64 P, [%0], %1, 0x989680;\n\t"
                 "@!P bra WL%=;\n\t}" :: "r"(a), "r"(par) : "memory");
}
__device__ __forceinline__ void bulk_cp(uint32_t dst, const void* src, uint32_t sz, uint32_t mb) {
    asm volatile("cp.async.bulk.shared::cta.global.mbarrier::complete_tx::bytes [%0], [%1], %2, [%3];"
                 :: "r"(dst), "l"(src), "r"(sz), "r"(mb) : "memory");
}
#define FENCE_ASYNC() asm volatile("fence.proxy.async.shared::cta;" ::: "memory")
__device__ __forceinline__ void ldsm4(uint32_t* r, uint32_t a) {
    asm volatile("ldmatrix.sync.aligned.m8n8.x4.shared.b16 {%0,%1,%2,%3}, [%4];"
                 : "=r"(r[0]), "=r"(r[1]), "=r"(r[2]), "=r"(r[3]) : "r"(a));
}
__device__ __forceinline__ void mma_bf16(float* c, const uint32_t* a, uint32_t b0, uint32_t b1) {
    asm volatile("mma.sync.aligned.m16n8k16.row.col.f32.bf16.bf16.f32 "
        "{%0,%1,%2,%3}, {%4,%5,%6,%7}, {%8,%9}, {%0,%1,%2,%3};"
        : "+f"(c[0]), "+f"(c[1]), "+f"(c[2]), "+f"(c[3])
        : "r"(a[0]), "r"(a[1]), "r"(a[2]), "r"(a[3]), "r"(b0), "r"(b1));
}

// act address (bytes) for element (n, plane value cv, phys index i)
__device__ __forceinline__ size_t act_off(int n, int cv, int i, int Th) {
    int row = i >> 1, p = i & 1;
    int c = cv >> 4, g = (cv >> 3) & 1;
    int sw = g ^ ((row >> 2) & 1);
    return (((size_t)(n * 32 + c) * 2 + p) * Th + row) * 32 + sw * 16 + (cv & 7) * 2;
}

// ---------- fused conv0 + GroupNorm + GELU + split, writes plane layout ----------
__global__ __launch_bounds__(256) void conv0_fused(
    const float* __restrict__ x, const float* __restrict__ W0,
    const float* __restrict__ g0, const float* __restrict__ b0,
    __nv_bfloat16* __restrict__ hi, __nv_bfloat16* __restrict__ lo)
{
    __shared__ float xs[L_IN];
    __shared__ float r1[8][32], r2[8][32];
    const int n = blockIdx.y, tid = threadIdx.x;
    const int lane = tid & 31, wid = tid >> 5;
    const int co = blockIdx.x * 32 + lane;

    float w[10];
#pragma unroll
    for (int k = 0; k < 10; ++k) w[k] = W0[co * 10 + k];
    const float* xr = x + (size_t)n * L_IN;
    for (int i = tid; i < L_IN; i += 256) xs[i] = xr[i];
    __syncthreads();

    float lsum = 0.f, lsq = 0.f;
    for (int t = wid; t < L0_; t += 8) {
        float s = 0.f;
#pragma unroll
        for (int k = 0; k < 10; ++k) s += xs[3 * t + k] * w[k];
        lsum += s; lsq += s * s;
    }
    r1[wid][lane] = lsum; r2[wid][lane] = lsq;
    __syncthreads();
    float tot = 0.f, tsq = 0.f;
#pragma unroll
    for (int i = 0; i < 8; ++i) { tot += r1[i][lane]; tsq += r2[i][lane]; }
    const float mu  = tot * (1.0f / L0_);
    const float var = tsq * (1.0f / L0_) - mu * mu;
    const float sc  = rsqrtf(var + 1e-5f) * g0[co];
    const float sh  = b0[co] - mu * sc;

    for (int t = wid; t < L0_; t += 8) {
        float s = 0.f;
#pragma unroll
        for (int k = 0; k < 10; ++k) s += xs[3 * t + k] * w[k];
        float v = gelu_exact(s * sc + sh);
        __nv_bfloat16 h = __float2bfloat16(v);
        size_t off = act_off(n, co, t, TH0);
        *(__nv_bfloat16*)((char*)hi + off) = h;
        *(__nv_bfloat16*)((char*)lo + off) = __float2bfloat16(v - __bfloat162float(h));
    }
}

// ---------- ALL weights fp32 [co][ci][kw] -> swizzled tiles [kslice][ci16][co512][32B] ----------
// one launch; slice s in [0,14): 0-2=W1, 3-5=W2, 6-8=W3, 9-11=W4, 12-13=W5
__global__ void prep_w_all(
    const float* __restrict__ W1, const float* __restrict__ W2,
    const float* __restrict__ W3, const float* __restrict__ W4,
    const float* __restrict__ W5,
    __nv_bfloat16* __restrict__ hi, __nv_bfloat16* __restrict__ lo)
{
    int idx = blockIdx.x * 256 + threadIdx.x;
    if (idx >= 14 * WSL) return;
    int s = idx >> 18, r = idx & (WSL - 1);
    int co = r >> 9, ci = r & 511;
    const float* W; int k, KW;
    if      (s < 3)  { W = W1; k = s;      KW = 3; }
    else if (s < 6)  { W = W2; k = s - 3;  KW = 3; }
    else if (s < 9)  { W = W3; k = s - 6;  KW = 3; }
    else if (s < 12) { W = W4; k = s - 9;  KW = 3; }
    else             { W = W5; k = s - 12; KW = 2; }
    float v = W[(size_t)(co * 512 + ci) * KW + k];
    __nv_bfloat16 h = __float2bfloat16(v);
    int sw = ((ci >> 3) & 1) ^ ((co >> 2) & 1);
    size_t off = ((size_t)(s * 32 + (ci >> 4)) * 512 + co) * 32 + sw * 16 + (ci & 7) * 2;
    *(__nv_bfloat16*)((char*)hi + off) = h;
    *(__nv_bfloat16*)((char*)lo + off) = __float2bfloat16(v - __bfloat162float(h));
}

// ---------- conv layer: bulk-copy staged, k-shared B, bf16x3 HMMA (term-major issue) ----------
// CTA 128co x NTt, 8 warps 4m x 2n (warp 32co x NT/2 t). 32 stages of ci16.
template<int KW, int NT, bool FP32OUT>
__global__ __launch_bounds__(256, 2) void conv_bulk(
    const __nv_bfloat16* __restrict__ xh, const __nv_bfloat16* __restrict__ xl,
    const __nv_bfloat16* __restrict__ wt_h, const __nv_bfloat16* __restrict__ wt_l,
    void* __restrict__ outA, __nv_bfloat16* __restrict__ outLo,
    int Lin, int Lout, int ThIn, int ThOut)
{
    extern __shared__ __align__(128) char smem[];
    constexpr int ROWS_E = NT + (KW == 3 ? 1 : 0);
    constexpr int ROWS_O = NT;
    constexpr int OFF_B  = KW * 8192;
    constexpr int BUF    = OFF_B + 2 * (ROWS_E + ROWS_O) * 32;
    constexpr int NN     = NT / 16;
    constexpr int NB     = NT / 32;
    const int tid = threadIdx.x, lane = tid & 31, wid = tid >> 5;
    const int wm = wid >> 1, wn = wid & 1;
    const int n = blockIdx.z, co0 = blockIdx.y * 128, t0 = blockIdx.x * NT;
    const uint32_t sb = s2u(smem);
    const uint32_t mb0 = sb + 2 * BUF;

    float acc[2][NN][4];
#pragma unroll
    for (int m = 0; m < 2; ++m)
#pragma unroll
        for (int nn = 0; nn < NN; ++nn)
#pragma unroll
            for (int i = 0; i < 4; ++i) acc[m][nn][i] = 0.f;

    auto load_stage = [&](int s) {
        const int c = s;
        const uint32_t bufb = sb + (uint32_t)(s & 1) * BUF;
        const uint32_t mb = mb0 + (uint32_t)(s & 1) * 8;
        mb_expect(mb, (uint32_t)(KW * 8192 + 2 * (ROWS_E + ROWS_O) * 32));
#pragma unroll
        for (int k = 0; k < KW; ++k) {
            size_t wo = ((size_t)(k * 32 + c) * 512 + co0) * 32;
            bulk_cp(bufb + k * 8192,        (const char*)wt_h + wo, 4096, mb);
            bulk_cp(bufb + k * 8192 + 4096, (const char*)wt_l + wo, 4096, mb);
        }
        size_t be = (((size_t)(n * 32 + c) * 2 + 0) * ThIn + t0) * 32;
        size_t bo = (((size_t)(n * 32 + c) * 2 + 1) * ThIn + t0) * 32;
        bulk_cp(bufb + OFF_B,                                  (const char*)xh + be, ROWS_E * 32, mb);
        bulk_cp(bufb + OFF_B + ROWS_E * 32,                    (const char*)xl + be, ROWS_E * 32, mb);
        bulk_cp(bufb + OFF_B + 2 * ROWS_E * 32,                (const char*)xh + bo, ROWS_O * 32, mb);
        bulk_cp(bufb + OFF_B + 2 * ROWS_E * 32 + ROWS_O * 32,  (const char*)xl + bo, ROWS_O * 32, mb);
    };

    if (tid == 0) { mb_init(mb0, 1); mb_init(mb0 + 8, 1); }
    __syncthreads();
    if (tid == 0) { FENCE_ASYNC(); load_stage(0); load_stage(1); }

    const int laneR = lane & 15, gsel = lane >> 4;
    for (int s = 0; s < 32; ++s) {
        mb_wait(mb0 + (uint32_t)(s & 1) * 8, (s >> 1) & 1);
        const uint32_t bufb = sb + (uint32_t)(s & 1) * BUF;
#pragma unroll
        for (int k = 0; k < KW; ++k) {
            uint32_t ah[2][4], al[2][4];
#pragma unroll
            for (int m = 0; m < 2; ++m) {
                int r = wm * 32 + m * 16 + laneR;
                uint32_t a = bufb + k * 8192 + r * 32 + ((gsel ^ ((r >> 2) & 1)) << 4);
                ldsm4(ah[m], a);
                ldsm4(al[m], a + 4096);
            }
            const int p = k & 1, kd = k >> 1;
            const uint32_t baseh = bufb + OFF_B + (p ? 2 * ROWS_E * 32 : 0);
            const uint32_t rsz = (p ? ROWS_O : ROWS_E) * 32;
#pragma unroll
            for (int b = 0; b < NB; ++b) {
                int r = wn * (NT / 2) + b * 16 + laneR + kd;
                uint32_t aB = baseh + r * 32 + ((gsel ^ ((r >> 2) & 1)) << 4);
                uint32_t bh[4], bl[4];
                ldsm4(bh, aB);
                ldsm4(bl, aB + rsz);
                // term-major: dependent HMMAs on the same accumulator spaced by 4
#pragma unroll
                for (int m = 0; m < 2; ++m)
#pragma unroll
                    for (int o = 0; o < 2; ++o)
                        mma_bf16(acc[m][b * 2 + o], ah[m], bh[o], bh[o + 2]);
#pragma unroll
                for (int m = 0; m < 2; ++m)
#pragma unroll
                    for (int o = 0; o < 2; ++o)
                        mma_bf16(acc[m][b * 2 + o], ah[m], bl[o], bl[o + 2]);
#pragma unroll
                for (int m = 0; m < 2; ++m)
#pragma unroll
                    for (int o = 0; o < 2; ++o)
                        mma_bf16(acc[m][b * 2 + o], al[m], bh[o], bh[o + 2]);
            }
        }
        __syncthreads();
        if (s + 2 < 32 && tid == 0) load_stage(s + 2);
    }

    if (FP32OUT) {
        float* outF = (float*)outA;
#pragma unroll
        for (int m = 0; m < 2; ++m) {
            const int coA = co0 + wm * 32 + m * 16 + (lane >> 2);
#pragma unroll
            for (int nn = 0; nn < NN; ++nn) {
                int tt = t0 + wn * (NT / 2) + nn * 8 + 2 * (lane & 3);
#pragma unroll
                for (int i = 0; i < 4; ++i) {
                    int t = tt + (i & 1), co = coA + (i >> 1) * 8;
                    if (t < Lout)
                        outF[((size_t)n * D_ + co) * T_ + t] = gelu_exact(acc[m][nn][i]);
                }
            }
        }
    } else {
        __nv_bfloat16* sHi = (__nv_bfloat16*)smem;
        __nv_bfloat16* sLo = (__nv_bfloat16*)(smem + NT * 272);
#pragma unroll
        for (int m = 0; m < 2; ++m) {
            const int coA = wm * 32 + m * 16 + (lane >> 2);
#pragma unroll
            for (int nn = 0; nn < NN; ++nn) {
                const int tt = wn * (NT / 2) + nn * 8 + 2 * (lane & 3);
#pragma unroll
                for (int i = 0; i < 4; ++i) {
                    int t = tt + (i & 1), co = coA + (i >> 1) * 8;
                    float g = gelu_exact(acc[m][nn][i]);
                    __nv_bfloat16 h = __float2bfloat16(g);
                    sHi[t * 136 + co] = h;
                    sLo[t * 136 + co] = __float2bfloat16(g - __bfloat162float(h));
                }
            }
        }
        __syncthreads();
        for (int idx = tid; idx < NT * 16; idx += 256) {
            int t = idx >> 4, gg = idx & 15;
            int tAbs = t0 + t;
            if (tAbs < Lout) {
                int row = tAbs >> 1, p = tAbs & 1;
                int coA = co0 + gg * 8;
                int c = coA >> 4, gb = (coA >> 3) & 1;
                int sw = gb ^ ((row >> 2) & 1);
                size_t off = (((size_t)(n * 32 + c) * 2 + p) * ThOut + row) * 32 + sw * 16;
                *(uint4*)((char*)outA + off)  = *(uint4*)(smem + t * 272 + gg * 16);
                *(uint4*)((char*)outLo + off) = *(uint4*)(smem + NT * 272 + t * 272 + gg * 16);
            }
        }
    }
}

// ---------- 1x1 channel fusion ----------
__global__ void fusion_kernel(const float* __restrict__ h, const float* __restrict__ fw,
                              const float* __restrict__ fb, float* __restrict__ ze)
{
    int idx = blockIdx.x * 256 + threadIdx.x;
    if (idx >= SECT) return;
    int b = idx / (D_ * T_);
    int r = idx - b * (D_ * T_);
    float s = fb[0];
    const float* hp = h + (size_t)b * C_ * D_ * T_ + r;
#pragma unroll 5
    for (int c = 0; c < C_; ++c) s += hp[(size_t)c * D_ * T_] * fw[c];
    ze[idx] = s;
}

// ---------- VQ argmin ----------
__global__ __launch_bounds__(256) void quantize_kernel(
    const float* __restrict__ ze, const float* __restrict__ cb, float* __restrict__ out)
{
    __shared__ __align__(16) float z[512];
    __shared__ float sd[256];
    __shared__ int   si[256];
    const int blk = blockIdx.x;
    const int b = blk / T_, t = blk - b * T_;
    const int tid = threadIdx.x;

    const float* zb = ze + (size_t)b * D_ * T_ + t;
    for (int d = tid; d < D_; d += 256) z[d] = zb[(size_t)d * T_];
    __syncthreads();

    float best = 3.4e38f; int bi = 0;
    for (int kk = tid; kk < KCODES; kk += 256) {
        const float4* cr = reinterpret_cast<const float4*>(cb + (size_t)kk * D_);
        const float4* zr = reinterpret_cast<const float4*>(z);
        float s = 0.f;
#pragma unroll 8
        for (int q = 0; q < 128; ++q) {
            float4 c4 = cr[q], z4 = zr[q];
            float d0 = z4.x - c4.x, d1 = z4.y - c4.y;
            float d2 = z4.z - c4.z, d3 = z4.w - c4.w;
            s += d0 * d0 + d1 * d1 + d2 * d2 + d3 * d3;
        }
        if (s < best) { best = s; bi = kk; }
    }
    sd[tid] = best; si[tid] = bi;
    __syncthreads();
    for (int off = 128; off; off >>= 1) {
        if (tid < off) {
            float od = sd[tid + off]; int oi = si[tid + off];
            if (od < sd[tid] || (od == sd[tid] && oi < si[tid])) { sd[tid] = od; si[tid] = oi; }
        }
        __syncthreads();
    }
    const int w = si[0];
    const float* crow = cb + (size_t)w * D_;
    const size_t base = (size_t)b * D_ * T_ + t;
    for (int d = tid; d < D_; d += 256) {
        float v = crow[d];
        out[base + (size_t)d * T_]            = v;
        out[2 * SECT + base + (size_t)d * T_] = v;
    }
}

// ---------- launch ----------
extern "C" void kernel_launch(void* const* d_in, const int* in_sizes, int n_in,
                              void* d_out, int out_size)
{
    const float* x  = (const float*)d_in[0];
    const float* W0 = (const float*)d_in[4];
    const float* g0 = (const float*)d_in[5];
    const float* b0 = (const float*)d_in[6];
    const float* W1 = (const float*)d_in[7];
    const float* W2 = (const float*)d_in[8];
    const float* W3 = (const float*)d_in[9];
    const float* W4 = (const float*)d_in[10];
    const float* W5 = (const float*)d_in[11];
    const float* fw = (const float*)d_in[12];
    const float* fb = (const float*)d_in[13];
    const float* cb = (const float*)d_in[14];
    float* out = (float*)d_out;

    float* pc5 = nullptr;
    __nv_bfloat16 *hA, *lA, *hB, *lB, *wh, *wl;
    cudaGetSymbolAddress((void**)&pc5, g_c5);
    cudaGetSymbolAddress((void**)&hA,  g_hiA);
    cudaGetSymbolAddress((void**)&lA,  g_loA);
    cudaGetSymbolAddress((void**)&hB,  g_hiB);
    cudaGetSymbolAddress((void**)&lB,  g_loB);
    cudaGetSymbolAddress((void**)&wh,  g_whi);
    cudaGetSymbolAddress((void**)&wl,  g_wlo);

    const int SM160 = 2 * (3 * 8192 + 2 * (161 + 160) * 32) + 16;  // 90256
    const int SM128 = 2 * (3 * 8192 + 2 * (129 + 128) * 32) + 16;  // 82064
    const int SM64  = 2 * (2 * 8192 + 2 * (64 + 64) * 32) + 16;    // 49168
    cudaFuncSetAttribute(conv_bulk<3, 160, false>, cudaFuncAttributeMaxDynamicSharedMemorySize, SM160);
    cudaFuncSetAttribute(conv_bulk<3, 128, false>, cudaFuncAttributeMaxDynamicSharedMemorySize, SM128);
    cudaFuncSetAttribute(conv_bulk<2, 64, true>,   cudaFuncAttributeMaxDynamicSharedMemorySize, SM64);

    // launches: 0=prep_all, 1=conv0, 2=conv1, 3=conv2, 4=conv3, 5=conv4 (ncu -s 5 target)
    prep_w_all<<<(14 * WSL + 255) / 256, 256>>>(W1, W2, W3, W4, W5, wh, wl);
    conv0_fused<<<dim3(16, NCH), 256>>>(x, W0, g0, b0, hA, lA);

    conv_bulk<3, 160, false><<<dim3(6, 4, NCH), 256, SM160>>>(hA, lA, wh + 0 * WSL, wl + 0 * WSL, hB, lB, 1831, 915, TH0, TH1);
    conv_bulk<3, 160, false><<<dim3(3, 4, NCH), 256, SM160>>>(hB, lB, wh + 3 * WSL, wl + 3 * WSL, hA, lA, 915, 457, TH1, TH2);
    conv_bulk<3, 128, false><<<dim3(2, 4, NCH), 256, SM128>>>(hA, lA, wh + 6 * WSL, wl + 6 * WSL, hB, lB, 457, 228, TH2, TH3);
    conv_bulk<3, 128, false><<<dim3(1, 4, NCH), 256, SM128>>>(hB, lB, wh + 9 * WSL, wl + 9 * WSL, hA, lA, 228, 113, TH3, TH4);
    conv_bulk<2, 64, true><<<dim3(1, 4, NCH), 256, SM64>>>(hA, lA, wh + 12 * WSL, wl + 12 * WSL, pc5, nullptr, 113, 56, TH4, 0);

    fusion_kernel<<<(SECT + 255) / 256, 256>>>(pc5, fw, fb, out + SECT);
    quantize_kernel<<<B_ * T_, 256>>>(out + SECT, cb, out);
}